// round 1
// baseline (speedup 1.0000x reference)
#include <cuda_runtime.h>
#include <cuda_bf16.h>
#include <string.h>

#define T_STEPS 8192
#define HID     1024
#define G4      4096   // 4*HID
#define INW     1024
#define NCTA    128

// ---------------- static device scratch (no runtime allocation) --------------
__device__ float    g_pre[(size_t)T_STEPS * G4];    // 128 MB: x-projection of gates
__device__ float    g_hall[(size_t)T_STEPS * HID];  // 32 MB: all hidden states
__device__ float    g_hring[2][HID];                // h double buffer
__device__ unsigned g_cnt[T_STEPS];                 // per-step arrival counters

// ---------------- small PTX helpers ------------------------------------------
__device__ __forceinline__ unsigned ld_acquire_u32(const unsigned* p) {
    unsigned v;
    asm volatile("ld.acquire.gpu.global.u32 %0, [%1];" : "=r"(v) : "l"(p) : "memory");
    return v;
}
__device__ __forceinline__ void red_release_add(unsigned* p, unsigned v) {
    asm volatile("red.release.gpu.global.add.u32 [%0], %1;" :: "l"(p), "r"(v) : "memory");
}
__device__ __forceinline__ float2 ffma2(float2 a, float2 b, float2 c) {
    unsigned long long A, B, C, D;
    memcpy(&A, &a, 8); memcpy(&B, &b, 8); memcpy(&C, &c, 8);
    asm("fma.rn.f32x2 %0, %1, %2, %3;" : "=l"(D) : "l"(A), "l"(B), "l"(C));
    float2 d; memcpy(&d, &D, 8); return d;
}
__device__ __forceinline__ float fsig(float x) {
    // 1/(1+e^-x); safe at extremes (exp->inf gives 0, exp->0 gives 1)
    return __fdividef(1.0f, 1.0f + __expf(-x));
}
__device__ __forceinline__ float ftanh_acc(float x) {
    float xc = fminf(fmaxf(x, -15.0f), 15.0f);
    float e  = __expf(2.0f * xc);
    return __fdividef(e - 1.0f, e + 1.0f);
}

// ---------------- init: zero the step counters --------------------------------
__global__ void init_cnt_kernel() {
    int i = blockIdx.x * blockDim.x + threadIdx.x;
    if (i < T_STEPS) g_cnt[i] = 0;
}

// ---------------- generic fp32 NT GEMM: C = A*B^T + bias ----------------------
// A: [M x K] row-major (lda), B: [N x K] row-major (ldb), C: [M x N] (ldc)
// BM=BN=128, BK=16, 256 threads, 8x8 microtile. M,N %128==0, K %16==0.
__device__ __forceinline__ void gemm_body(
    const float* __restrict__ A, int lda,
    const float* __restrict__ B, int ldb,
    const float* __restrict__ bias,
    float* __restrict__ C, int ldc, int K)
{
    __shared__ float As[16][132];
    __shared__ float Bs[16][132];

    const int tid  = threadIdx.x;
    const int tx   = tid & 15;          // N-dir microtile
    const int ty   = tid >> 4;          // M-dir microtile
    const int brow = blockIdx.y * 128;
    const int bcol = blockIdx.x * 128;
    const int lr   = tid >> 2;          // 0..63 (load row)
    const int lc   = (tid & 3) << 2;    // 0,4,8,12 (load col group)

    float acc[8][8];
#pragma unroll
    for (int i = 0; i < 8; i++)
#pragma unroll
        for (int j = 0; j < 8; j++) acc[i][j] = 0.0f;

    const float* Aptr = A + (size_t)(brow + lr) * lda + lc;
    const float* Bptr = B + (size_t)(bcol + lr) * ldb + lc;

    for (int k0 = 0; k0 < K; k0 += 16) {
#pragma unroll
        for (int r = 0; r < 2; r++) {
            float4 va = *(const float4*)(Aptr + (size_t)(64 * r) * lda + k0);
            As[lc + 0][lr + 64 * r] = va.x;
            As[lc + 1][lr + 64 * r] = va.y;
            As[lc + 2][lr + 64 * r] = va.z;
            As[lc + 3][lr + 64 * r] = va.w;
            float4 vb = *(const float4*)(Bptr + (size_t)(64 * r) * ldb + k0);
            Bs[lc + 0][lr + 64 * r] = vb.x;
            Bs[lc + 1][lr + 64 * r] = vb.y;
            Bs[lc + 2][lr + 64 * r] = vb.z;
            Bs[lc + 3][lr + 64 * r] = vb.w;
        }
        __syncthreads();
#pragma unroll
        for (int kk = 0; kk < 16; kk++) {
            float ra[8], rb[8];
            *(float4*)(ra)     = *(const float4*)&As[kk][ty * 8];
            *(float4*)(ra + 4) = *(const float4*)&As[kk][ty * 8 + 4];
            *(float4*)(rb)     = *(const float4*)&Bs[kk][tx * 8];
            *(float4*)(rb + 4) = *(const float4*)&Bs[kk][tx * 8 + 4];
#pragma unroll
            for (int i = 0; i < 8; i++)
#pragma unroll
                for (int j = 0; j < 8; j++)
                    acc[i][j] = fmaf(ra[i], rb[j], acc[i][j]);
        }
        __syncthreads();
    }

    float bv[8];
    *(float4*)(bv)     = *(const float4*)&bias[bcol + tx * 8];
    *(float4*)(bv + 4) = *(const float4*)&bias[bcol + tx * 8 + 4];
#pragma unroll
    for (int i = 0; i < 8; i++) {
        float4 o0, o1;
        o0.x = acc[i][0] + bv[0]; o0.y = acc[i][1] + bv[1];
        o0.z = acc[i][2] + bv[2]; o0.w = acc[i][3] + bv[3];
        o1.x = acc[i][4] + bv[4]; o1.y = acc[i][5] + bv[5];
        o1.z = acc[i][6] + bv[6]; o1.w = acc[i][7] + bv[7];
        float* crow = C + (size_t)(brow + ty * 8 + i) * ldc + bcol + tx * 8;
        *(float4*)(crow)     = o0;
        *(float4*)(crow + 4) = o1;
    }
}

__global__ void __launch_bounds__(256, 2) gemm_pre_kernel(
    const float* __restrict__ x, const float* __restrict__ Ww,
    const float* __restrict__ Wb)
{
    // PRE[t][j] = sum_k x[t][k] * Ww[j][k] + Wb[j]  (k < 1024, ldb = 2048)
    gemm_body(x, INW, Ww, INW + HID, Wb, g_pre, G4, INW);
}

__global__ void __launch_bounds__(256, 2) gemm_out_kernel(
    const float* __restrict__ ow, const float* __restrict__ ob,
    float* __restrict__ out)
{
    // Y[t][o] = sum_u H_all[t][u] * ow[o][u] + ob[o]
    gemm_body(g_hall, HID, ow, HID, ob, out, HID, HID);
}

// ---------------- persistent LSTM recurrence ----------------------------------
// 128 CTAs x 512 threads. CTA c owns hidden units u in [8c, 8c+8).
// Warp w (w<8):  rows rA=u0+w (i-gate), rB=rA+1024 (f-gate)
// Warp w (w>=8): rows rA=u0+(w-8)+2048 (g-gate), rB=rA+1024 (o-gate)
// Each thread holds 16 k-pairs (float2) per row in registers (64 regs of weights).
__global__ void __launch_bounds__(512, 1) lstm_kernel(const float* __restrict__ Ww)
{
    const int tid  = threadIdx.x;
    const int w    = tid >> 5;
    const int lane = tid & 31;
    const int d    = w & 7;
    const int u    = blockIdx.x * 8 + d;
    const int rA   = (w < 8) ? u : (u + 2048);
    const int rB   = rA + 1024;

    __shared__ float  sh[HID];
    __shared__ float4 gq[8];     // (i, f, g, o) per unit

    // load recurrent weights (columns 1024..2047 of Ww) into registers
    float2 wa[16], wb[16];
    const float2* WA = (const float2*)(Ww + (size_t)rA * (INW + HID) + INW);
    const float2* WB = (const float2*)(Ww + (size_t)rB * (INW + HID) + INW);
#pragma unroll
    for (int i = 0; i < 16; i++) {
        wa[i] = WA[lane + 32 * i];
        wb[i] = WB[lane + 32 * i];
    }

    float c_state = 0.0f;   // live only in threads 0..7

    for (int t = 0; t < T_STEPS; t++) {
        // PRE prefetch (independent of h) — issued before the spin
        float preA = 0.0f, preB = 0.0f;
        if (lane == 0) {
            preA = g_pre[(size_t)t * G4 + rA];
            preB = g_pre[(size_t)t * G4 + rB];
        }

        if (t == 0) {
            ((float2*)sh)[tid] = make_float2(0.0f, 0.0f);
        } else {
            if (tid == 0) {
                while (ld_acquire_u32(&g_cnt[t - 1]) != NCTA) { }
            }
            __syncthreads();
            ((float2*)sh)[tid] = ((const float2*)g_hring[(t - 1) & 1])[tid];
        }
        __syncthreads();

        // dot products: lane handles k-pairs {lane+32i}, i=0..15 (k = 2*pair)
        float2 aA = make_float2(0.0f, 0.0f);
        float2 aB = make_float2(0.0f, 0.0f);
#pragma unroll
        for (int i = 0; i < 16; i++) {
            float2 h2 = ((const float2*)sh)[lane + 32 * i];
            aA = ffma2(wa[i], h2, aA);
            aB = ffma2(wb[i], h2, aB);
        }
        float sA = aA.x + aA.y;
        float sB = aB.x + aB.y;
#pragma unroll
        for (int off = 16; off > 0; off >>= 1) {
            sA += __shfl_down_sync(0xffffffffu, sA, off);
            sB += __shfl_down_sync(0xffffffffu, sB, off);
        }
        if (lane == 0) {
            if (w < 8) { gq[d].x = sA + preA; gq[d].y = sB + preB; }
            else       { gq[d].z = sA + preA; gq[d].w = sB + preB; }
        }
        __syncthreads();

        if (tid < 8) {
            float4 G = gq[tid];
            float ig = fsig(G.x);
            float fg = fsig(G.y);
            float gg = ftanh_acc(G.z);
            float og = fsig(G.w);
            c_state = fg * c_state + ig * gg;
            float h = og * ftanh_acc(c_state);
            int uu = blockIdx.x * 8 + tid;
            g_hring[t & 1][uu] = h;
            g_hall[(size_t)t * HID + uu] = h;
        }
        __syncthreads();
        if (tid == 0) red_release_add(&g_cnt[t], 1u);
    }
}

// ---------------- launch -------------------------------------------------------
extern "C" void kernel_launch(void* const* d_in, const int* in_sizes, int n_in,
                              void* d_out, int out_size)
{
    const float* x   = (const float*)d_in[0];  // [8192, 1, 1024]
    const float* Ww  = (const float*)d_in[1];  // [4096, 2048]
    const float* Wb  = (const float*)d_in[2];  // [4096]
    const float* ow  = (const float*)d_in[3];  // [1024, 1024]
    const float* ob  = (const float*)d_in[4];  // [1024]
    float*       out = (float*)d_out;          // [8192, 1, 1024]

    init_cnt_kernel<<<(T_STEPS + 255) / 256, 256>>>();

    dim3 gridA(G4 / 128, T_STEPS / 128);       // 32 x 64
    gemm_pre_kernel<<<gridA, 256>>>(x, Ww, Wb);

    lstm_kernel<<<NCTA, 512>>>(Ww);

    dim3 gridC(HID / 128, T_STEPS / 128);      // 8 x 64
    gemm_out_kernel<<<gridC, 256>>>(ow, ob, out);
}

// round 4
// speedup vs baseline: 1.3310x; 1.3310x over previous
#include <cuda_runtime.h>
#include <cuda_bf16.h>
#include <string.h>

#define T_STEPS 8192
#define HID     1024
#define G4      4096   // 4*HID
#define INW     1024
#define NCTA    128

// ---------------- static device scratch (no runtime allocation) --------------
__device__ float g_pre[(size_t)T_STEPS * G4];    // 128 MB: x-projection of gates
__device__ float g_hall[(size_t)T_STEPS * HID];  // 32 MB: all hidden states
// tagged h ring: each element = (tag:32 << 32) | float_bits(h).  slot = t&1, tag = t+1
__device__ __align__(16) unsigned long long g_htag[2][HID];

// ---------------- small PTX helpers ------------------------------------------
__device__ __forceinline__ ulonglong2 ld_tag_v2(const unsigned long long* p) {
    ulonglong2 v;
    asm volatile("ld.relaxed.gpu.global.v2.u64 {%0,%1}, [%2];"
                 : "=l"(v.x), "=l"(v.y) : "l"(p) : "memory");
    return v;
}
__device__ __forceinline__ void st_tag_u64(unsigned long long* p, unsigned long long v) {
    asm volatile("st.relaxed.gpu.global.u64 [%0], %1;" :: "l"(p), "l"(v) : "memory");
}
__device__ __forceinline__ float2 ffma2(float2 a, float2 b, float2 c) {
    unsigned long long A, B, C, D;
    memcpy(&A, &a, 8); memcpy(&B, &b, 8); memcpy(&C, &c, 8);
    asm("fma.rn.f32x2 %0, %1, %2, %3;" : "=l"(D) : "l"(A), "l"(B), "l"(C));
    float2 d; memcpy(&d, &D, 8); return d;
}
__device__ __forceinline__ float2 fpack2(float a) {
    float2 r;
    unsigned long long R;
    asm("mov.b64 %0, {%1, %1};" : "=l"(R) : "f"(a));
    memcpy(&r, &R, 8); return r;
}
__device__ __forceinline__ float fsig(float x) {
    return __fdividef(1.0f, 1.0f + __expf(-x));
}
__device__ __forceinline__ float ftanh_acc(float x) {
    float xc = fminf(fmaxf(x, -15.0f), 15.0f);
    float e  = __expf(2.0f * xc);
    return __fdividef(e - 1.0f, e + 1.0f);
}

// ---------------- init: zero the tagged ring ----------------------------------
__global__ void init_tags_kernel() {
    int i = blockIdx.x * blockDim.x + threadIdx.x;
    if (i < 2 * HID) ((unsigned long long*)g_htag)[i] = 0ull;
}

// ---------------- generic fp32 NT GEMM: C = A*B^T + bias (FFMA2 microtile) ----
// A: [M x K] row-major (lda), B: [N x K] row-major (ldb), C: [M x N] (ldc)
// BM=BN=128, BK=16, 256 threads, 8x8 microtile (as 8x4 float2).
__device__ __forceinline__ void gemm_body(
    const float* __restrict__ A, int lda,
    const float* __restrict__ B, int ldb,
    const float* __restrict__ bias,
    float* __restrict__ C, int ldc, int K)
{
    __shared__ float As[16][132];
    __shared__ float Bs[16][132];

    const int tid  = threadIdx.x;
    const int tx   = tid & 15;          // N-dir microtile
    const int ty   = tid >> 4;          // M-dir microtile
    const int brow = blockIdx.y * 128;
    const int bcol = blockIdx.x * 128;
    const int lr   = tid >> 2;          // 0..63 (load row)
    const int lc   = (tid & 3) << 2;    // 0,4,8,12 (load col group)

    float2 acc[8][4];
#pragma unroll
    for (int i = 0; i < 8; i++)
#pragma unroll
        for (int j = 0; j < 4; j++) acc[i][j] = make_float2(0.0f, 0.0f);

    const float* Aptr = A + (size_t)(brow + lr) * lda + lc;
    const float* Bptr = B + (size_t)(bcol + lr) * ldb + lc;

    for (int k0 = 0; k0 < K; k0 += 16) {
#pragma unroll
        for (int r = 0; r < 2; r++) {
            float4 va = *(const float4*)(Aptr + (size_t)(64 * r) * lda + k0);
            As[lc + 0][lr + 64 * r] = va.x;
            As[lc + 1][lr + 64 * r] = va.y;
            As[lc + 2][lr + 64 * r] = va.z;
            As[lc + 3][lr + 64 * r] = va.w;
            float4 vb = *(const float4*)(Bptr + (size_t)(64 * r) * ldb + k0);
            Bs[lc + 0][lr + 64 * r] = vb.x;
            Bs[lc + 1][lr + 64 * r] = vb.y;
            Bs[lc + 2][lr + 64 * r] = vb.z;
            Bs[lc + 3][lr + 64 * r] = vb.w;
        }
        __syncthreads();
#pragma unroll
        for (int kk = 0; kk < 16; kk++) {
            float  ra[8];
            float2 rb[4];
            *(float4*)(ra)     = *(const float4*)&As[kk][ty * 8];
            *(float4*)(ra + 4) = *(const float4*)&As[kk][ty * 8 + 4];
            *(float4*)(&rb[0]) = *(const float4*)&Bs[kk][tx * 8];
            *(float4*)(&rb[2]) = *(const float4*)&Bs[kk][tx * 8 + 4];
#pragma unroll
            for (int i = 0; i < 8; i++) {
                float2 a2 = fpack2(ra[i]);
#pragma unroll
                for (int j = 0; j < 4; j++)
                    acc[i][j] = ffma2(a2, rb[j], acc[i][j]);
            }
        }
        __syncthreads();
    }

    float2 bv[4];
    *(float4*)(&bv[0]) = *(const float4*)&bias[bcol + tx * 8];
    *(float4*)(&bv[2]) = *(const float4*)&bias[bcol + tx * 8 + 4];
#pragma unroll
    for (int i = 0; i < 8; i++) {
        float4 o0, o1;
        o0.x = acc[i][0].x + bv[0].x; o0.y = acc[i][0].y + bv[0].y;
        o0.z = acc[i][1].x + bv[1].x; o0.w = acc[i][1].y + bv[1].y;
        o1.x = acc[i][2].x + bv[2].x; o1.y = acc[i][2].y + bv[2].y;
        o1.z = acc[i][3].x + bv[3].x; o1.w = acc[i][3].y + bv[3].y;
        float* crow = C + (size_t)(brow + ty * 8 + i) * ldc + bcol + tx * 8;
        *(float4*)(crow)     = o0;
        *(float4*)(crow + 4) = o1;
    }
}

__global__ void __launch_bounds__(256, 2) gemm_pre_kernel(
    const float* __restrict__ x, const float* __restrict__ Ww,
    const float* __restrict__ Wb)
{
    gemm_body(x, INW, Ww, INW + HID, Wb, g_pre, G4, INW);
}

__global__ void __launch_bounds__(256, 2) gemm_out_kernel(
    const float* __restrict__ ow, const float* __restrict__ ob,
    float* __restrict__ out)
{
    gemm_body(g_hall, HID, ow, HID, ob, out, HID, HID);
}

// ---------------- persistent LSTM recurrence ----------------------------------
// 128 CTAs x 512 threads. CTA c owns hidden units u in [8c, 8c+8).
// Warp w (w<8):  rows rA=u0+w (i-gate), rB=rA+1024 (f-gate)
// Warp w (w>=8): rows rA=u0+(w-8)+2048 (g-gate), rB=rA+1024 (o-gate)
// h exchange: tagged 64-bit words, 2-slot ring — poll fuses flag + data load.
__global__ void __launch_bounds__(512, 1) lstm_kernel(const float* __restrict__ Ww)
{
    const int tid  = threadIdx.x;
    const int w    = tid >> 5;
    const int lane = tid & 31;
    const int d    = w & 7;
    const int u    = blockIdx.x * 8 + d;
    const int rA   = (w < 8) ? u : (u + 2048);
    const int rB   = rA + 1024;

    __shared__ float  sh[HID];
    __shared__ float4 gq[8];     // (i, f, g, o) per unit

    // recurrent weights (columns 1024..2047 of Ww) live in registers
    float2 wa[16], wb[16];
    const float2* WA = (const float2*)(Ww + (size_t)rA * (INW + HID) + INW);
    const float2* WB = (const float2*)(Ww + (size_t)rB * (INW + HID) + INW);
#pragma unroll
    for (int i = 0; i < 16; i++) {
        wa[i] = WA[lane + 32 * i];
        wb[i] = WB[lane + 32 * i];
    }

    float c_state = 0.0f;   // live only in threads 0..7

    for (int t = 0; t < T_STEPS; t++) {
        // PRE prefetch (independent of h) — issued before the poll
        float preA = 0.0f, preB = 0.0f;
        if (lane == 0) {
            preA = g_pre[(size_t)t * G4 + rA];
            preB = g_pre[(size_t)t * G4 + rB];
        }

        if (t == 0) {
            ((float2*)sh)[tid] = make_float2(0.0f, 0.0f);
        } else {
            // fused flag+data: poll own 2 tagged elements until tag == t
            const unsigned long long* src = &g_htag[(t - 1) & 1][2 * tid];
            const unsigned long long want = (unsigned long long)t;
            ulonglong2 v;
            for (;;) {
                v = ld_tag_v2(src);
                if ((v.x >> 32) == want && (v.y >> 32) == want) break;
            }
            ((float2*)sh)[tid] = make_float2(
                __uint_as_float((unsigned)(v.x & 0xffffffffu)),
                __uint_as_float((unsigned)(v.y & 0xffffffffu)));
        }
        __syncthreads();

        // dot products: lane handles k-pairs {lane+32i}, i=0..15
        float2 aA = make_float2(0.0f, 0.0f);
        float2 aB = make_float2(0.0f, 0.0f);
#pragma unroll
        for (int i = 0; i < 16; i++) {
            float2 h2 = ((const float2*)sh)[lane + 32 * i];
            aA = ffma2(wa[i], h2, aA);
            aB = ffma2(wb[i], h2, aB);
        }
        float sA = aA.x + aA.y;
        float sB = aB.x + aB.y;
#pragma unroll
        for (int off = 16; off > 0; off >>= 1) {
            sA += __shfl_down_sync(0xffffffffu, sA, off);
            sB += __shfl_down_sync(0xffffffffu, sB, off);
        }
        if (lane == 0) {
            if (w < 8) { gq[d].x = sA + preA; gq[d].y = sB + preB; }
            else       { gq[d].z = sA + preA; gq[d].w = sB + preB; }
        }
        __syncthreads();

        if (tid < 8) {
            float4 G = gq[tid];
            float ig = fsig(G.x);
            float fg = fsig(G.y);
            float gg = ftanh_acc(G.z);
            float og = fsig(G.w);
            c_state = fg * c_state + ig * gg;
            float h = og * ftanh_acc(c_state);
            int uu = blockIdx.x * 8 + tid;
            unsigned long long word =
                ((unsigned long long)(t + 1) << 32) | (unsigned long long)__float_as_uint(h);
            st_tag_u64(&g_htag[t & 1][uu], word);
            g_hall[(size_t)t * HID + uu] = h;
        }
        // no trailing barrier needed: next-iteration sh/gq writes are ordered
        // behind this step's reads by the two barriers above (see analysis)
    }
}

// ---------------- launch -------------------------------------------------------
extern "C" void kernel_launch(void* const* d_in, const int* in_sizes, int n_in,
                              void* d_out, int out_size)
{
    const float* x   = (const float*)d_in[0];  // [8192, 1, 1024]
    const float* Ww  = (const float*)d_in[1];  // [4096, 2048]
    const float* Wb  = (const float*)d_in[2];  // [4096]
    const float* ow  = (const float*)d_in[3];  // [1024, 1024]
    const float* ob  = (const float*)d_in[4];  // [1024]
    float*       out = (float*)d_out;          // [8192, 1, 1024]

    init_tags_kernel<<<(2 * HID + 255) / 256, 256>>>();

    dim3 gridA(G4 / 128, T_STEPS / 128);       // 32 x 64
    gemm_pre_kernel<<<gridA, 256>>>(x, Ww, Wb);

    lstm_kernel<<<NCTA, 512>>>(Ww);

    dim3 gridC(HID / 128, T_STEPS / 128);      // 8 x 64
    gemm_out_kernel<<<gridC, 256>>>(ow, ob, out);
}